// round 10
// baseline (speedup 1.0000x reference)
#include <cuda_runtime.h>
#include <cuda_fp16.h>
#include <cstdint>
#include <math.h>

#define BB 4
#define NN 4096
#define CC 768
#define NHEADS 12
#define NPTS 4
#define HDIM 64
#define HIDDEN 3072
#define MROWS (BB*NN)   // 16384
#define NOFF (NHEADS*NPTS*2)   // 96

// ---------------- scratch (allocation-free: __device__ globals) ----------------
__device__ __half g_h   [(size_t)MROWS*CC];
__device__ __half g_qkv [(size_t)MROWS*3*CC];
__device__ float  g_off [(size_t)MROWS*NOFF];
__device__ __half g_att [(size_t)MROWS*CC];
__device__ float  g_x2  [(size_t)MROWS*CC];
__device__ __half g_h2  [(size_t)MROWS*CC];
__device__ __half g_mid [(size_t)MROWS*HIDDEN];
__device__ __half g_qkvw_h[(size_t)3*CC*CC];
__device__ __half g_pw_h  [(size_t)CC*CC];
__device__ __half g_f1w_h [(size_t)HIDDEN*CC];
__device__ __half g_f2w_h [(size_t)CC*HIDDEN];
__device__ __half g_offw_h[(size_t)128*CC];          // 96 real rows + 32 zero rows

// ================= PTX helpers =================
__device__ __forceinline__ uint32_t s2u(const void* p) {
    uint32_t r;
    asm("{ .reg .u64 t; cvta.to.shared.u64 t, %1; cvt.u32.u64 %0, t; }" : "=r"(r) : "l"(p));
    return r;
}
__device__ __forceinline__ void cp16(uint32_t dst, const void* src) {
    asm volatile("cp.async.cg.shared.global [%0], [%1], 16;" :: "r"(dst), "l"(src));
}
__device__ __forceinline__ void cp_commit() {
    asm volatile("cp.async.commit_group;" ::: "memory");
}
template<int N>
__device__ __forceinline__ void cp_wait() {
    asm volatile("cp.async.wait_group %0;" :: "n"(N) : "memory");
}
__device__ __forceinline__ void ldm_x4(uint32_t* r, uint32_t addr) {
    asm volatile("ldmatrix.sync.aligned.m8n8.x4.shared.b16 {%0,%1,%2,%3}, [%4];"
        : "=r"(r[0]), "=r"(r[1]), "=r"(r[2]), "=r"(r[3]) : "r"(addr));
}
__device__ __forceinline__ void mma16816(float* c, const uint32_t* a, const uint32_t* b) {
    asm volatile("mma.sync.aligned.m16n8k16.row.col.f32.f16.f16.f32 "
        "{%0,%1,%2,%3}, {%4,%5,%6,%7}, {%8,%9}, {%0,%1,%2,%3};"
        : "+f"(c[0]), "+f"(c[1]), "+f"(c[2]), "+f"(c[3])
        : "r"(a[0]), "r"(a[1]), "r"(a[2]), "r"(a[3]), "r"(b[0]), "r"(b[1]));
}

// ================= fp16 HMMA GEMM =================
// 128x128 CTA tile, 8 warps of 32x64, BK=64 (half the sync events of BK=32),
// 3-stage cp.async, two barriers/chunk (proven-safe structure), 2 CTAs/SM.
// EPI: 0 = bias->fp16 ; 1 = bias+fp32 residual->fp32 ; 2 = bias+GELU->fp16 ; 3 = bias->fp32
#define BK 64
#define HSTRIDE 72                     // halves per smem row (144B, conflict-free for ldmatrix)
#define ATILE_B (128*HSTRIDE*2)        // 18432 bytes
#define STAGE_B (2*ATILE_B)            // 36864
#define NSTG 3
#define HG_SMEM (NSTG*STAGE_B)         // 110592

__device__ __forceinline__ void load_chunk(uint32_t sA, uint32_t sB,
    const __half* A, const __half* B, int lda, int K, int bm, int bn, int c, int tid)
{
    #pragma unroll
    for (int j = 0; j < 4; j++) {
        int i = tid * 4 + j;
        int row = i >> 3, q = i & 7;
        cp16(sA + row * (HSTRIDE*2) + q * 16,
             A + (size_t)(bm + row) * lda + c * BK + q * 8);
        cp16(sB + row * (HSTRIDE*2) + q * 16,
             B + (size_t)(bn + row) * K + c * BK + q * 8);
    }
}

template<int EPI>
__global__ void __launch_bounds__(256, 2) hgemm(
    const __half* __restrict__ A, const __half* __restrict__ W,
    const float* __restrict__ bias, const float* __restrict__ res,
    __half* __restrict__ outh, float* __restrict__ outf,
    int lda, int K, int ldc, int Nn)
{
    extern __shared__ char smem[];
    const uint32_t sb = s2u(smem);
    const int tid  = threadIdx.x;
    const int lane = tid & 31;
    const int w    = tid >> 5;
    const int wm   = w & 3;          // 4 m-blocks of 32
    const int wn   = w >> 2;         // 2 n-blocks of 64
    const int bm = blockIdx.y * 128;
    const int bn = blockIdx.x * 128;
    const int nk = K / BK;

    float c[2][8][4];
    #pragma unroll
    for (int mi = 0; mi < 2; mi++)
        #pragma unroll
        for (int ni = 0; ni < 8; ni++)
            #pragma unroll
            for (int q = 0; q < 4; q++) c[mi][ni][q] = 0.f;

    const int arow = (lane & 7) + ((lane >> 3) & 1) * 8;
    const int akof = (lane >> 4) * 8;
    const int brow = ((lane >> 4) & 1) * 8 + (lane & 7);
    const int bkof = ((lane >> 3) & 1) * 8;

    load_chunk(sb, sb + ATILE_B, A, W, lda, K, bm, bn, 0, tid); cp_commit();
    load_chunk(sb + STAGE_B, sb + STAGE_B + ATILE_B, A, W, lda, K, bm, bn, 1, tid); cp_commit();

    for (int cch = 0; cch < nk; cch++) {
        int st = cch % NSTG;
        if (cch + 1 < nk) cp_wait<1>(); else cp_wait<0>();
        __syncthreads();
        if (cch + 2 < nk) {
            int st2 = (cch + 2) % NSTG;
            load_chunk(sb + st2 * STAGE_B, sb + st2 * STAGE_B + ATILE_B,
                       A, W, lda, K, bm, bn, cch + 2, tid);
            cp_commit();
        }
        uint32_t sA = sb + st * STAGE_B;
        uint32_t sB = sA + ATILE_B;
        #pragma unroll
        for (int kk = 0; kk < 4; kk++) {
            uint32_t a[2][4], b[4][4];
            #pragma unroll
            for (int mi = 0; mi < 2; mi++)
                ldm_x4(a[mi], sA + (wm*32 + mi*16 + arow) * (HSTRIDE*2)
                              + (kk*16 + akof) * 2);
            #pragma unroll
            for (int nt = 0; nt < 4; nt++)
                ldm_x4(b[nt], sB + (wn*64 + nt*16 + brow) * (HSTRIDE*2)
                              + (kk*16 + bkof) * 2);
            #pragma unroll
            for (int mi = 0; mi < 2; mi++)
                #pragma unroll
                for (int ni = 0; ni < 8; ni++)
                    mma16816(c[mi][ni], a[mi], &b[ni >> 1][(ni & 1) * 2]);
        }
        __syncthreads();
    }

    // epilogue
    const int g = lane >> 2;
    const int tc = (lane & 3) * 2;
    #pragma unroll
    for (int mi = 0; mi < 2; mi++) {
        #pragma unroll
        for (int ni = 0; ni < 8; ni++) {
            int row = bm + wm*32 + mi*16 + g;
            int col = bn + wn*64 + ni*8 + tc;
            if (EPI == 3 && col >= Nn) continue;
            float b0 = bias[col], b1 = bias[col + 1];
            #pragma unroll
            for (int half = 0; half < 2; half++) {
                int r = row + half * 8;
                float v0 = c[mi][ni][half*2 + 0] + b0;
                float v1 = c[mi][ni][half*2 + 1] + b1;
                if (EPI == 1) {
                    size_t o = (size_t)r * ldc + col;
                    outf[o]     = v0 + res[o];
                    outf[o + 1] = v1 + res[o + 1];
                } else if (EPI == 3) {
                    size_t o = (size_t)r * ldc + col;
                    outf[o]     = v0;
                    outf[o + 1] = v1;
                } else {
                    if (EPI == 2) {
                        v0 = 0.5f * v0 * (1.0f + erff(v0 * 0.70710678118654752f));
                        v1 = 0.5f * v1 * (1.0f + erff(v1 * 0.70710678118654752f));
                    }
                    *(__half2*)&outh[(size_t)r * ldc + col] =
                        __floats2half2_rn(v0, v1);
                }
            }
        }
    }
}

// ---------------- fp32 -> fp16 convert (all 5 weights in one launch) ----------
#define W1N (3*CC*CC)
#define W2N (CC*CC)
#define W3N (HIDDEN*CC)
#define W4N (CC*HIDDEN)
#define W5R (NOFF*CC)
#define W5N (128*CC)
__global__ void f2h_all(const float* __restrict__ s1, __half* __restrict__ d1,
                        const float* __restrict__ s2, __half* __restrict__ d2,
                        const float* __restrict__ s3, __half* __restrict__ d3,
                        const float* __restrict__ s4, __half* __restrict__ d4,
                        const float* __restrict__ s5, __half* __restrict__ d5)
{
    int i = blockIdx.x * blockDim.x + threadIdx.x;
    int stride = gridDim.x * blockDim.x;
    const int total = W1N + W2N + W3N + W4N + W5N;
    for (; i < total; i += stride) {
        int j = i;
        if (j < W1N) { d1[j] = __float2half(s1[j]); continue; }
        j -= W1N;
        if (j < W2N) { d2[j] = __float2half(s2[j]); continue; }
        j -= W2N;
        if (j < W3N) { d3[j] = __float2half(s3[j]); continue; }
        j -= W3N;
        if (j < W4N) { d4[j] = __float2half(s4[j]); continue; }
        j -= W4N;
        d5[j] = (j < W5R) ? __float2half(s5[j]) : __float2half(0.f);
    }
}

// ---------------- LayerNorm: warp-per-row, shuffle-only reduction ----------------
__global__ void __launch_bounds__(256) ln_kernel(
    const float* __restrict__ x, const float* __restrict__ w,
    const float* __restrict__ b, __half* __restrict__ out)
{
    int row  = blockIdx.x * 8 + (threadIdx.x >> 5);
    int lane = threadIdx.x & 31;
    const float4* xr = (const float4*)(x + (size_t)row * CC);
    const float4* w4 = (const float4*)w;
    const float4* b4 = (const float4*)b;
    __half2* orow = (__half2*)(out + (size_t)row * CC);

    float4 v[6];
    float s = 0.f, s2 = 0.f;
    #pragma unroll
    for (int i = 0; i < 6; i++) {
        v[i] = xr[lane + 32 * i];
        s  += v[i].x + v[i].y + v[i].z + v[i].w;
        s2 += v[i].x*v[i].x + v[i].y*v[i].y + v[i].z*v[i].z + v[i].w*v[i].w;
    }
    #pragma unroll
    for (int o = 16; o; o >>= 1) {
        s  += __shfl_xor_sync(0xffffffffu, s,  o);
        s2 += __shfl_xor_sync(0xffffffffu, s2, o);
    }
    float mean = s * (1.0f / CC);
    float rstd = rsqrtf(s2 * (1.0f / CC) - mean * mean + 1e-5f);

    #pragma unroll
    for (int i = 0; i < 6; i++) {
        int idx = lane + 32 * i;
        float4 ww = w4[idx];
        float4 bb = b4[idx];
        float r0 = (v[i].x - mean) * rstd * ww.x + bb.x;
        float r1 = (v[i].y - mean) * rstd * ww.y + bb.y;
        float r2 = (v[i].z - mean) * rstd * ww.z + bb.z;
        float r3 = (v[i].w - mean) * rstd * ww.w + bb.w;
        orow[idx * 2 + 0] = __floats2half2_rn(r0, r1);
        orow[idx * 2 + 1] = __floats2half2_rn(r2, r3);
    }
}

// ---------------- Fused deformable attention: one warp per (b, n, h) -----------
__global__ void attn_kernel(const __half* __restrict__ qkv, const float* __restrict__ off,
                            const float* __restrict__ ref, __half* __restrict__ out)
{
    int gw = (blockIdx.x * blockDim.x + threadIdx.x) >> 5;
    int lane = threadIdx.x & 31;
    if (gw >= BB * NN * NHEADS) return;
    int h  = gw % NHEADS;
    int bn = gw / NHEADS;
    int b  = bn / NN;

    float refx = ref[(size_t)bn * 2 + 0];
    float refy = ref[(size_t)bn * 2 + 1];

    const __half2* qkv2 = (const __half2*)qkv;
    size_t qidx = ((size_t)bn * (3 * CC) + h * HDIM) / 2 + lane;
    float2 q = __half22float2(qkv2[qidx]);

    const float* obp = off + (size_t)bn * NOFF + h * NPTS * 2;
    size_t imgbase2 = ((size_t)b * NN * (3 * CC)) / 2;
    int choff2 = (h * HDIM) / 2 + lane;

    float dots[NPTS];
    float2 vv[NPTS];
    #pragma unroll
    for (int p = 0; p < NPTS; p++) {
        float xp = refx * 64.f + obp[p * 2 + 0] - 0.5f;
        float yp = refy * 64.f + obp[p * 2 + 1] - 0.5f;
        float x0f = floorf(xp), y0f = floorf(yp);
        float wx = xp - x0f, wy = yp - y0f;
        int ix0 = (int)x0f, iy0 = (int)y0f;

        float cw[4] = {(1.f - wx) * (1.f - wy), wx * (1.f - wy),
                       (1.f - wx) * wy,          wx * wy};
        int cx[4] = {ix0, ix0 + 1, ix0, ix0 + 1};
        int cy[4] = {iy0, iy0, iy0 + 1, iy0 + 1};

        float2 ks = make_float2(0.f, 0.f), vs = make_float2(0.f, 0.f);
        #pragma unroll
        for (int c = 0; c < 4; c++) {
            if (cx[c] >= 0 && cx[c] < 64 && cy[c] >= 0 && cy[c] < 64) {
                size_t base2 = imgbase2 + (size_t)(cy[c] * 64 + cx[c]) * ((3 * CC) / 2) + choff2;
                float wgt = cw[c];
                float2 k2 = __half22float2(qkv2[base2 + CC / 2]);
                float2 v2 = __half22float2(qkv2[base2 + CC]);
                ks.x += wgt * k2.x; ks.y += wgt * k2.y;
                vs.x += wgt * v2.x; vs.y += wgt * v2.y;
            }
        }
        float d = q.x * ks.x + q.y * ks.y;
        #pragma unroll
        for (int o = 16; o; o >>= 1) d += __shfl_xor_sync(0xffffffffu, d, o);
        dots[p] = d * 0.125f;
        vv[p] = vs;
    }

    float mx = fmaxf(fmaxf(dots[0], dots[1]), fmaxf(dots[2], dots[3]));
    float e[NPTS], den = 0.f;
    #pragma unroll
    for (int p = 0; p < NPTS; p++) { e[p] = expf(dots[p] - mx); den += e[p]; }
    float inv = 1.f / den;
    float o0 = 0.f, o1 = 0.f;
    #pragma unroll
    for (int p = 0; p < NPTS; p++) {
        float a = e[p] * inv;
        o0 += a * vv[p].x; o1 += a * vv[p].y;
    }

    __half2* out2 = (__half2*)out;
    out2[((size_t)bn * CC + h * HDIM) / 2 + lane] = __floats2half2_rn(o0, o1);
}

// ---------------- launch ----------------
extern "C" void kernel_launch(void* const* d_in, const int* in_sizes, int n_in,
                              void* d_out, int out_size)
{
    const float* x    = (const float*)d_in[0];
    const float* ref  = (const float*)d_in[1];
    const float* n1w  = (const float*)d_in[2];
    const float* n1b  = (const float*)d_in[3];
    const float* qkvw = (const float*)d_in[4];
    const float* qkvb = (const float*)d_in[5];
    const float* offw = (const float*)d_in[6];
    const float* offb = (const float*)d_in[7];
    const float* pw   = (const float*)d_in[8];
    const float* pb   = (const float*)d_in[9];
    const float* n2w  = (const float*)d_in[10];
    const float* n2b  = (const float*)d_in[11];
    const float* f1w  = (const float*)d_in[12];
    const float* f1b  = (const float*)d_in[13];
    const float* f2w  = (const float*)d_in[14];
    const float* f2b  = (const float*)d_in[15];
    float* out = (float*)d_out;

    __half *h_, *qkv_, *att_, *h2_, *mid_, *qkvw_h, *pw_h, *f1w_h, *f2w_h, *offw_h;
    float *off_, *x2_;
    cudaGetSymbolAddress((void**)&h_,     g_h);
    cudaGetSymbolAddress((void**)&qkv_,   g_qkv);
    cudaGetSymbolAddress((void**)&off_,   g_off);
    cudaGetSymbolAddress((void**)&att_,   g_att);
    cudaGetSymbolAddress((void**)&x2_,    g_x2);
    cudaGetSymbolAddress((void**)&h2_,    g_h2);
    cudaGetSymbolAddress((void**)&mid_,   g_mid);
    cudaGetSymbolAddress((void**)&qkvw_h, g_qkvw_h);
    cudaGetSymbolAddress((void**)&pw_h,   g_pw_h);
    cudaGetSymbolAddress((void**)&f1w_h,  g_f1w_h);
    cudaGetSymbolAddress((void**)&f2w_h,  g_f2w_h);
    cudaGetSymbolAddress((void**)&offw_h, g_offw_h);

    cudaFuncSetAttribute(hgemm<0>, cudaFuncAttributeMaxDynamicSharedMemorySize, HG_SMEM);
    cudaFuncSetAttribute(hgemm<1>, cudaFuncAttributeMaxDynamicSharedMemorySize, HG_SMEM);
    cudaFuncSetAttribute(hgemm<2>, cudaFuncAttributeMaxDynamicSharedMemorySize, HG_SMEM);
    cudaFuncSetAttribute(hgemm<3>, cudaFuncAttributeMaxDynamicSharedMemorySize, HG_SMEM);

    // 0. weight conversions to fp16 (single launch)
    f2h_all<<<2048, 256>>>(qkvw, qkvw_h, pw, pw_h, f1w, f1w_h, f2w, f2w_h, offw, offw_h);

    // 1. h = LN1(x)
    ln_kernel<<<MROWS / 8, 256>>>(x, n1w, n1b, h_);
    // 2. qkv = h @ qkv_w.T + qkv_b  [16384, 2304]
    hgemm<0><<<dim3(18, 128), 256, HG_SMEM>>>(h_, qkvw_h, qkvb, nullptr,
                                              qkv_, nullptr, CC, CC, 3 * CC, 3 * CC);
    // 3. offsets = q @ off_w.T + off_b  [16384, 96]
    hgemm<3><<<dim3(1, 128), 256, HG_SMEM>>>(qkv_, offw_h, offb, nullptr,
                                             nullptr, off_, 3 * CC, CC, NOFF, NOFF);
    // 4. fused grid-sample attention
    attn_kernel<<<(BB * NN * NHEADS * 32) / 256, 256>>>(qkv_, off_, ref, att_);
    // 5. x2 = x + att @ proj_w.T + proj_b
    hgemm<1><<<dim3(6, 128), 256, HG_SMEM>>>(att_, pw_h, pb, x,
                                             nullptr, x2_, CC, CC, CC, CC);
    // 6. h2 = LN2(x2)
    ln_kernel<<<MROWS / 8, 256>>>(x2_, n2w, n2b, h2_);
    // 7. mid = gelu(h2 @ fc1_w.T + fc1_b)  [16384, 3072]
    hgemm<2><<<dim3(24, 128), 256, HG_SMEM>>>(h2_, f1w_h, f1b, nullptr,
                                              mid_, nullptr, CC, CC, HIDDEN, HIDDEN);
    // 8. out = x2 + mid @ fc2_w.T + fc2_b
    hgemm<1><<<dim3(6, 128), 256, HG_SMEM>>>(mid_, f2w_h, f2b, x2_,
                                             nullptr, out, HIDDEN, HIDDEN, CC, CC);
}

// round 12
// speedup vs baseline: 1.1308x; 1.1308x over previous
#include <cuda_runtime.h>
#include <cuda_fp16.h>
#include <cstdint>
#include <math.h>

#define BB 4
#define NN 4096
#define CC 768
#define NHEADS 12
#define NPTS 4
#define HDIM 64
#define HIDDEN 3072
#define MROWS (BB*NN)   // 16384
#define NOFF (NHEADS*NPTS*2)   // 96

// ---------------- scratch (allocation-free: __device__ globals) ----------------
__device__ __half g_h   [(size_t)MROWS*CC];
__device__ __half g_qkv [(size_t)MROWS*3*CC];
__device__ float  g_off [(size_t)MROWS*NOFF];
__device__ __half g_att [(size_t)MROWS*CC];
__device__ float  g_x2  [(size_t)MROWS*CC];
__device__ __half g_h2  [(size_t)MROWS*CC];
__device__ __half g_mid [(size_t)MROWS*HIDDEN];
__device__ __half g_qkvw_h[(size_t)3*CC*CC];
__device__ __half g_pw_h  [(size_t)CC*CC];
__device__ __half g_f1w_h [(size_t)HIDDEN*CC];
__device__ __half g_f2w_h [(size_t)CC*HIDDEN];
__device__ __half g_offw_h[(size_t)128*CC];          // 96 real rows + 32 zero rows

// ================= PTX helpers =================
__device__ __forceinline__ uint32_t s2u(const void* p) {
    uint32_t r;
    asm("{ .reg .u64 t; cvta.to.shared.u64 t, %1; cvt.u32.u64 %0, t; }" : "=r"(r) : "l"(p));
    return r;
}
__device__ __forceinline__ void cp16(uint32_t dst, const void* src) {
    asm volatile("cp.async.cg.shared.global [%0], [%1], 16;" :: "r"(dst), "l"(src));
}
__device__ __forceinline__ void cp_commit() {
    asm volatile("cp.async.commit_group;" ::: "memory");
}
template<int N>
__device__ __forceinline__ void cp_wait() {
    asm volatile("cp.async.wait_group %0;" :: "n"(N) : "memory");
}
__device__ __forceinline__ void ldm_x4(uint32_t* r, uint32_t addr) {
    asm volatile("ldmatrix.sync.aligned.m8n8.x4.shared.b16 {%0,%1,%2,%3}, [%4];"
        : "=r"(r[0]), "=r"(r[1]), "=r"(r[2]), "=r"(r[3]) : "r"(addr));
}
__device__ __forceinline__ void mma16816(float* c, const uint32_t* a, const uint32_t* b) {
    asm volatile("mma.sync.aligned.m16n8k16.row.col.f32.f16.f16.f32 "
        "{%0,%1,%2,%3}, {%4,%5,%6,%7}, {%8,%9}, {%0,%1,%2,%3};"
        : "+f"(c[0]), "+f"(c[1]), "+f"(c[2]), "+f"(c[3])
        : "r"(a[0]), "r"(a[1]), "r"(a[2]), "r"(a[3]), "r"(b[0]), "r"(b[1]));
}

// ================= fp16 HMMA GEMM (R9-proven config — FROZEN) =================
// 128x128 CTA tile, 8 warps of 32x64, BK=32, 3-stage cp.async, 2 CTAs/SM.
// EPI: 0 = bias->fp16 ; 1 = bias+fp32 residual->fp32 ; 2 = bias+GELU->fp16 ; 3 = bias->fp32
#define BK 32
#define HSTRIDE 40
#define ATILE_B (128*HSTRIDE*2)        // 10240 bytes
#define STAGE_B (2*ATILE_B)            // 20480
#define NSTG 3
#define HG_SMEM (NSTG*STAGE_B)         // 61440

__device__ __forceinline__ void load_chunk(uint32_t sA, uint32_t sB,
    const __half* A, const __half* B, int lda, int K, int bm, int bn, int c, int tid)
{
    #pragma unroll
    for (int j = 0; j < 2; j++) {
        int i = tid * 2 + j;
        int row = i >> 2, q = i & 3;
        cp16(sA + row * (HSTRIDE*2) + q * 16,
             A + (size_t)(bm + row) * lda + c * BK + q * 8);
        cp16(sB + row * (HSTRIDE*2) + q * 16,
             B + (size_t)(bn + row) * K + c * BK + q * 8);
    }
}

template<int EPI>
__global__ void __launch_bounds__(256, 2) hgemm(
    const __half* __restrict__ A, const __half* __restrict__ W,
    const float* __restrict__ bias, const float* __restrict__ res,
    __half* __restrict__ outh, float* __restrict__ outf,
    int lda, int K, int ldc, int Nn)
{
    extern __shared__ char smem[];
    const uint32_t sb = s2u(smem);
    const int tid  = threadIdx.x;
    const int lane = tid & 31;
    const int w    = tid >> 5;
    const int wm   = w & 3;          // 4 m-blocks of 32
    const int wn   = w >> 2;         // 2 n-blocks of 64
    const int bm = blockIdx.y * 128;
    const int bn = blockIdx.x * 128;
    const int nk = K / BK;

    float c[2][8][4];
    #pragma unroll
    for (int mi = 0; mi < 2; mi++)
        #pragma unroll
        for (int ni = 0; ni < 8; ni++)
            #pragma unroll
            for (int q = 0; q < 4; q++) c[mi][ni][q] = 0.f;

    const int arow = (lane & 7) + ((lane >> 3) & 1) * 8;
    const int akof = (lane >> 4) * 8;
    const int brow = ((lane >> 4) & 1) * 8 + (lane & 7);
    const int bkof = ((lane >> 3) & 1) * 8;

    load_chunk(sb, sb + ATILE_B, A, W, lda, K, bm, bn, 0, tid); cp_commit();
    load_chunk(sb + STAGE_B, sb + STAGE_B + ATILE_B, A, W, lda, K, bm, bn, 1, tid); cp_commit();

    for (int cch = 0; cch < nk; cch++) {
        int st = cch % NSTG;
        if (cch + 1 < nk) cp_wait<1>(); else cp_wait<0>();
        __syncthreads();
        if (cch + 2 < nk) {
            int st2 = (cch + 2) % NSTG;
            load_chunk(sb + st2 * STAGE_B, sb + st2 * STAGE_B + ATILE_B,
                       A, W, lda, K, bm, bn, cch + 2, tid);
            cp_commit();
        }
        uint32_t sA = sb + st * STAGE_B;
        uint32_t sB = sA + ATILE_B;
        #pragma unroll
        for (int kk = 0; kk < 2; kk++) {
            uint32_t a[2][4], b[4][4];
            #pragma unroll
            for (int mi = 0; mi < 2; mi++)
                ldm_x4(a[mi], sA + (wm*32 + mi*16 + arow) * (HSTRIDE*2)
                              + (kk*16 + akof) * 2);
            #pragma unroll
            for (int nt = 0; nt < 4; nt++)
                ldm_x4(b[nt], sB + (wn*64 + nt*16 + brow) * (HSTRIDE*2)
                              + (kk*16 + bkof) * 2);
            #pragma unroll
            for (int mi = 0; mi < 2; mi++)
                #pragma unroll
                for (int ni = 0; ni < 8; ni++)
                    mma16816(c[mi][ni], a[mi], &b[ni >> 1][(ni & 1) * 2]);
        }
        __syncthreads();
    }

    // epilogue
    const int g = lane >> 2;
    const int tc = (lane & 3) * 2;
    #pragma unroll
    for (int mi = 0; mi < 2; mi++) {
        #pragma unroll
        for (int ni = 0; ni < 8; ni++) {
            int row = bm + wm*32 + mi*16 + g;
            int col = bn + wn*64 + ni*8 + tc;
            if (EPI == 3 && col >= Nn) continue;
            float b0 = bias[col], b1 = bias[col + 1];
            #pragma unroll
            for (int half = 0; half < 2; half++) {
                int r = row + half * 8;
                float v0 = c[mi][ni][half*2 + 0] + b0;
                float v1 = c[mi][ni][half*2 + 1] + b1;
                if (EPI == 1) {
                    size_t o = (size_t)r * ldc + col;
                    outf[o]     = v0 + res[o];
                    outf[o + 1] = v1 + res[o + 1];
                } else if (EPI == 3) {
                    size_t o = (size_t)r * ldc + col;
                    outf[o]     = v0;
                    outf[o + 1] = v1;
                } else {
                    if (EPI == 2) {
                        v0 = 0.5f * v0 * (1.0f + erff(v0 * 0.70710678118654752f));
                        v1 = 0.5f * v1 * (1.0f + erff(v1 * 0.70710678118654752f));
                    }
                    *(__half2*)&outh[(size_t)r * ldc + col] =
                        __floats2half2_rn(v0, v1);
                }
            }
        }
    }
}

// ---------------- LayerNorm body: warp-per-row (8 rows per 256-thread block) ----
__device__ __forceinline__ void ln_rows(
    const float* __restrict__ x, const float* __restrict__ w,
    const float* __restrict__ b, __half* __restrict__ out, int blk)
{
    int row  = blk * 8 + (threadIdx.x >> 5);
    int lane = threadIdx.x & 31;
    const float4* xr = (const float4*)(x + (size_t)row * CC);
    const float4* w4 = (const float4*)w;
    const float4* b4 = (const float4*)b;
    __half2* orow = (__half2*)(out + (size_t)row * CC);

    float4 v[6];
    float s = 0.f, s2 = 0.f;
    #pragma unroll
    for (int i = 0; i < 6; i++) {
        v[i] = xr[lane + 32 * i];
        s  += v[i].x + v[i].y + v[i].z + v[i].w;
        s2 += v[i].x*v[i].x + v[i].y*v[i].y + v[i].z*v[i].z + v[i].w*v[i].w;
    }
    #pragma unroll
    for (int o = 16; o; o >>= 1) {
        s  += __shfl_xor_sync(0xffffffffu, s,  o);
        s2 += __shfl_xor_sync(0xffffffffu, s2, o);
    }
    float mean = s * (1.0f / CC);
    float rstd = rsqrtf(s2 * (1.0f / CC) - mean * mean + 1e-5f);

    #pragma unroll
    for (int i = 0; i < 6; i++) {
        int idx = lane + 32 * i;
        float4 ww = w4[idx];
        float4 bb = b4[idx];
        float r0 = (v[i].x - mean) * rstd * ww.x + bb.x;
        float r1 = (v[i].y - mean) * rstd * ww.y + bb.y;
        float r2 = (v[i].z - mean) * rstd * ww.z + bb.z;
        float r3 = (v[i].w - mean) * rstd * ww.w + bb.w;
        orow[idx * 2 + 0] = __floats2half2_rn(r0, r1);
        orow[idx * 2 + 1] = __floats2half2_rn(r2, r3);
    }
}

__global__ void __launch_bounds__(256) ln_kernel(
    const float* __restrict__ x, const float* __restrict__ w,
    const float* __restrict__ b, __half* __restrict__ out)
{
    ln_rows(x, w, b, out, blockIdx.x);
}

// ---------------- Fused LN1 + weight conversion (one launch) -------------------
// Blocks [0, 2048): LN1 of 8 rows each. Blocks [2048, 4096): weight f2h grid-stride.
#define W1N (3*CC*CC)
#define W2N (CC*CC)
#define W3N (HIDDEN*CC)
#define W4N (CC*HIDDEN)
#define W5R (NOFF*CC)
#define W5N (128*CC)
#define LNBLKS (MROWS/8)
#define F2HBLKS 2048
__global__ void __launch_bounds__(256) ln1_f2h(
    const float* __restrict__ x,  const float* __restrict__ n1w,
    const float* __restrict__ n1b, __half* __restrict__ hout,
    const float* __restrict__ s1, __half* __restrict__ d1,
    const float* __restrict__ s2, __half* __restrict__ d2,
    const float* __restrict__ s3, __half* __restrict__ d3,
    const float* __restrict__ s4, __half* __restrict__ d4,
    const float* __restrict__ s5, __half* __restrict__ d5)
{
    if (blockIdx.x < LNBLKS) {
        ln_rows(x, n1w, n1b, hout, blockIdx.x);
        return;
    }
    int i = (blockIdx.x - LNBLKS) * blockDim.x + threadIdx.x;
    int stride = F2HBLKS * blockDim.x;
    const int total = W1N + W2N + W3N + W4N + W5N;
    for (; i < total; i += stride) {
        int j = i;
        if (j < W1N) { d1[j] = __float2half(s1[j]); continue; }
        j -= W1N;
        if (j < W2N) { d2[j] = __float2half(s2[j]); continue; }
        j -= W2N;
        if (j < W3N) { d3[j] = __float2half(s3[j]); continue; }
        j -= W3N;
        if (j < W4N) { d4[j] = __float2half(s4[j]); continue; }
        j -= W4N;
        d5[j] = (j < W5R) ? __float2half(s5[j]) : __float2half(0.f);
    }
}

// ---------------- Fused deformable attention: one warp per (b, n, h) -----------
// Interleaved reductions: all 16 corner gathers issue before any shuffle tree.
__global__ void attn_kernel(const __half* __restrict__ qkv, const float* __restrict__ off,
                            const float* __restrict__ ref, __half* __restrict__ out)
{
    int gw = (blockIdx.x * blockDim.x + threadIdx.x) >> 5;
    int lane = threadIdx.x & 31;
    if (gw >= BB * NN * NHEADS) return;
    int h  = gw % NHEADS;
    int bn = gw / NHEADS;
    int b  = bn / NN;

    float refx = ref[(size_t)bn * 2 + 0];
    float refy = ref[(size_t)bn * 2 + 1];

    const __half2* qkv2 = (const __half2*)qkv;
    size_t qidx = ((size_t)bn * (3 * CC) + h * HDIM) / 2 + lane;
    float2 q = __half22float2(qkv2[qidx]);

    const float* obp = off + (size_t)bn * NOFF + h * NPTS * 2;
    size_t imgbase2 = ((size_t)b * NN * (3 * CC)) / 2;
    int choff2 = (h * HDIM) / 2 + lane;

    float dots[NPTS];
    float2 vv[NPTS];
    #pragma unroll
    for (int p = 0; p < NPTS; p++) {
        float xp = refx * 64.f + obp[p * 2 + 0] - 0.5f;
        float yp = refy * 64.f + obp[p * 2 + 1] - 0.5f;
        float x0f = floorf(xp), y0f = floorf(yp);
        float wx = xp - x0f, wy = yp - y0f;
        int ix0 = (int)x0f, iy0 = (int)y0f;

        float cw[4] = {(1.f - wx) * (1.f - wy), wx * (1.f - wy),
                       (1.f - wx) * wy,          wx * wy};
        int cx[4] = {ix0, ix0 + 1, ix0, ix0 + 1};
        int cy[4] = {iy0, iy0, iy0 + 1, iy0 + 1};

        float2 ks = make_float2(0.f, 0.f), vs = make_float2(0.f, 0.f);
        #pragma unroll
        for (int c = 0; c < 4; c++) {
            if (cx[c] >= 0 && cx[c] < 64 && cy[c] >= 0 && cy[c] < 64) {
                size_t base2 = imgbase2 + (size_t)(cy[c] * 64 + cx[c]) * ((3 * CC) / 2) + choff2;
                float wgt = cw[c];
                float2 k2 = __half22float2(qkv2[base2 + CC / 2]);
                float2 v2 = __half22float2(qkv2[base2 + CC]);
                ks.x += wgt * k2.x; ks.y += wgt * k2.y;
                vs.x += wgt * v2.x; vs.y += wgt * v2.y;
            }
        }
        dots[p] = q.x * ks.x + q.y * ks.y;   // per-lane partial; reduce later
        vv[p] = vs;
    }

    // interleaved shuffle reductions: 4 independent chains pipeline each other
    #pragma unroll
    for (int o = 16; o; o >>= 1) {
        #pragma unroll
        for (int p = 0; p < NPTS; p++)
            dots[p] += __shfl_xor_sync(0xffffffffu, dots[p], o);
    }
    #pragma unroll
    for (int p = 0; p < NPTS; p++) dots[p] *= 0.125f;

    float mx = fmaxf(fmaxf(dots[0], dots[1]), fmaxf(dots[2], dots[3]));
    float e[NPTS], den = 0.f;
    #pragma unroll
    for (int p = 0; p < NPTS; p++) { e[p] = expf(dots[p] - mx); den += e[p]; }
    float inv = 1.f / den;
    float o0 = 0.f, o1 = 0.f;
    #pragma unroll
    for (int p = 0; p < NPTS; p++) {
        float a = e[p] * inv;
        o0 += a * vv[p].x; o1 += a * vv[p].y;
    }

    __half2* out2 = (__half2*)out;
    out2[((size_t)bn * CC + h * HDIM) / 2 + lane] = __floats2half2_rn(o0, o1);
}

// ---------------- launch ----------------
extern "C" void kernel_launch(void* const* d_in, const int* in_sizes, int n_in,
                              void* d_out, int out_size)
{
    const float* x    = (const float*)d_in[0];
    const float* ref  = (const float*)d_in[1];
    const float* n1w  = (const float*)d_in[2];
    const float* n1b  = (const float*)d_in[3];
    const float* qkvw = (const float*)d_in[4];
    const float* qkvb = (const float*)d_in[5];
    const float* offw = (const float*)d_in[6];
    const float* offb = (const float*)d_in[7];
    const float* pw   = (const float*)d_in[8];
    const float* pb   = (const float*)d_in[9];
    const float* n2w  = (const float*)d_in[10];
    const float* n2b  = (const float*)d_in[11];
    const float* f1w  = (const float*)d_in[12];
    const float* f1b  = (const float*)d_in[13];
    const float* f2w  = (const float*)d_in[14];
    const float* f2b  = (const float*)d_in[15];
    float* out = (float*)d_out;

    __half *h_, *qkv_, *att_, *h2_, *mid_, *qkvw_h, *pw_h, *f1w_h, *f2w_h, *offw_h;
    float *off_, *x2_;
    cudaGetSymbolAddress((void**)&h_,     g_h);
    cudaGetSymbolAddress((void**)&qkv_,   g_qkv);
    cudaGetSymbolAddress((void**)&off_,   g_off);
    cudaGetSymbolAddress((void**)&att_,   g_att);
    cudaGetSymbolAddress((void**)&x2_,    g_x2);
    cudaGetSymbolAddress((void**)&h2_,    g_h2);
    cudaGetSymbolAddress((void**)&mid_,   g_mid);
    cudaGetSymbolAddress((void**)&qkvw_h, g_qkvw_h);
    cudaGetSymbolAddress((void**)&pw_h,   g_pw_h);
    cudaGetSymbolAddress((void**)&f1w_h,  g_f1w_h);
    cudaGetSymbolAddress((void**)&f2w_h,  g_f2w_h);
    cudaGetSymbolAddress((void**)&offw_h, g_offw_h);

    cudaFuncSetAttribute(hgemm<0>, cudaFuncAttributeMaxDynamicSharedMemorySize, HG_SMEM);
    cudaFuncSetAttribute(hgemm<1>, cudaFuncAttributeMaxDynamicSharedMemorySize, HG_SMEM);
    cudaFuncSetAttribute(hgemm<2>, cudaFuncAttributeMaxDynamicSharedMemorySize, HG_SMEM);
    cudaFuncSetAttribute(hgemm<3>, cudaFuncAttributeMaxDynamicSharedMemorySize, HG_SMEM);

    // 0+1. LN1 and all weight conversions in one launch
    ln1_f2h<<<LNBLKS + F2HBLKS, 256>>>(x, n1w, n1b, h_,
                                       qkvw, qkvw_h, pw, pw_h, f1w, f1w_h,
                                       f2w, f2w_h, offw, offw_h);
    // 2. qkv = h @ qkv_w.T + qkv_b  [16384, 2304]
    hgemm<0><<<dim3(18, 128), 256, HG_SMEM>>>(h_, qkvw_h, qkvb, nullptr,
                                              qkv_, nullptr, CC, CC, 3 * CC, 3 * CC);
    // 3. offsets = q @ off_w.T + off_b  [16384, 96]
    hgemm<3><<<dim3(1, 128), 256, HG_SMEM>>>(qkv_, offw_h, offb, nullptr,
                                             nullptr, off_, 3 * CC, CC, NOFF, NOFF);
    // 4. fused grid-sample attention
    attn_kernel<<<(BB * NN * NHEADS * 32) / 256, 256>>>(qkv_, off_, ref, att_);
    // 5. x2 = x + att @ proj_w.T + proj_b
    hgemm<1><<<dim3(6, 128), 256, HG_SMEM>>>(att_, pw_h, pb, x,
                                             nullptr, x2_, CC, CC, CC, CC);
    // 6. h2 = LN2(x2)
    ln_kernel<<<MROWS / 8, 256>>>(x2_, n2w, n2b, h2_);
    // 7. mid = gelu(h2 @ fc1_w.T + fc1_b)  [16384, 3072]
    hgemm<2><<<dim3(24, 128), 256, HG_SMEM>>>(h2_, f1w_h, f1b, nullptr,
                                              mid_, nullptr, CC, CC, HIDDEN, HIDDEN);
    // 8. out = x2 + mid @ fc2_w.T + fc2_b
    hgemm<1><<<dim3(6, 128), 256, HG_SMEM>>>(mid_, f2w_h, f2b, x2_,
                                             nullptr, out, HIDDEN, HIDDEN, CC, CC);
}

// round 16
// speedup vs baseline: 1.1546x; 1.0210x over previous
#include <cuda_runtime.h>
#include <cuda_fp16.h>
#include <cstdint>
#include <math.h>

#define BB 4
#define NN 4096
#define CC 768
#define NHEADS 12
#define NPTS 4
#define HDIM 64
#define HIDDEN 3072
#define MROWS (BB*NN)   // 16384
#define NOFF (NHEADS*NPTS*2)   // 96

// ---------------- scratch (allocation-free: __device__ globals) ----------------
__device__ __half g_h   [(size_t)MROWS*CC];
__device__ __half g_qkv [(size_t)MROWS*3*CC];
__device__ float  g_off [(size_t)MROWS*NOFF];
__device__ __half g_att [(size_t)MROWS*CC];
__device__ float  g_x2  [(size_t)MROWS*CC];
__device__ __half g_h2  [(size_t)MROWS*CC];
__device__ __half g_mid [(size_t)MROWS*HIDDEN];
__device__ __half g_qkvw_h[(size_t)3*CC*CC];
__device__ __half g_pw_h  [(size_t)CC*CC];
__device__ __half g_f1w_h [(size_t)HIDDEN*CC];
__device__ __half g_f2w_h [(size_t)CC*HIDDEN];
__device__ __half g_offw_h[(size_t)128*CC];          // 96 real rows + 32 zero rows

// ================= PTX helpers =================
__device__ __forceinline__ uint32_t s2u(const void* p) {
    uint32_t r;
    asm("{ .reg .u64 t; cvta.to.shared.u64 t, %1; cvt.u32.u64 %0, t; }" : "=r"(r) : "l"(p));
    return r;
}
__device__ __forceinline__ void cp16(uint32_t dst, const void* src) {
    asm volatile("cp.async.cg.shared.global [%0], [%1], 16;" :: "r"(dst), "l"(src));
}
__device__ __forceinline__ void cp_commit() {
    asm volatile("cp.async.commit_group;" ::: "memory");
}
template<int N>
__device__ __forceinline__ void cp_wait() {
    asm volatile("cp.async.wait_group %0;" :: "n"(N) : "memory");
}
__device__ __forceinline__ void ldm_x4(uint32_t* r, uint32_t addr) {
    asm volatile("ldmatrix.sync.aligned.m8n8.x4.shared.b16 {%0,%1,%2,%3}, [%4];"
        : "=r"(r[0]), "=r"(r[1]), "=r"(r[2]), "=r"(r[3]) : "r"(addr));
}
__device__ __forceinline__ void mma16816(float* c, const uint32_t* a, const uint32_t* b) {
    asm volatile("mma.sync.aligned.m16n8k16.row.col.f32.f16.f16.f32 "
        "{%0,%1,%2,%3}, {%4,%5,%6,%7}, {%8,%9}, {%0,%1,%2,%3};"
        : "+f"(c[0]), "+f"(c[1]), "+f"(c[2]), "+f"(c[3])
        : "r"(a[0]), "r"(a[1]), "r"(a[2]), "r"(a[3]), "r"(b[0]), "r"(b[1]));
}

// ================= fp16 HMMA GEMM (R9-proven config — FROZEN) =================
// 128x128 CTA tile, 8 warps of 32x64, BK=32, 3-stage cp.async, 2 CTAs/SM.
// EPI: 0 = bias->fp16 ; 1 = bias+fp32 residual->fp32 ; 2 = bias+GELU->fp16 ; 3 = bias->fp32
#define BK 32
#define HSTRIDE 40
#define ATILE_B (128*HSTRIDE*2)        // 10240 bytes
#define STAGE_B (2*ATILE_B)            // 20480
#define NSTG 3
#define HG_SMEM (NSTG*STAGE_B)         // 61440

__device__ __forceinline__ void load_chunk(uint32_t sA, uint32_t sB,
    const __half* A, const __half* B, int lda, int K, int bm, int bn, int c, int tid)
{
    #pragma unroll
    for (int j = 0; j < 2; j++) {
        int i = tid * 2 + j;
        int row = i >> 2, q = i & 3;
        cp16(sA + row * (HSTRIDE*2) + q * 16,
             A + (size_t)(bm + row) * lda + c * BK + q * 8);
        cp16(sB + row * (HSTRIDE*2) + q * 16,
             B + (size_t)(bn + row) * K + c * BK + q * 8);
    }
}

template<int EPI>
__global__ void __launch_bounds__(256, 2) hgemm(
    const __half* __restrict__ A, const __half* __restrict__ W,
    const float* __restrict__ bias, const float* __restrict__ res,
    __half* __restrict__ outh, float* __restrict__ outf,
    int lda, int K, int ldc, int Nn)
{
    extern __shared__ char smem[];
    const uint32_t sb = s2u(smem);
    const int tid  = threadIdx.x;
    const int lane = tid & 31;
    const int w    = tid >> 5;
    const int wm   = w & 3;          // 4 m-blocks of 32
    const int wn   = w >> 2;         // 2 n-blocks of 64
    const int bm = blockIdx.y * 128;
    const int bn = blockIdx.x * 128;
    const int nk = K / BK;

    float c[2][8][4];
    #pragma unroll
    for (int mi = 0; mi < 2; mi++)
        #pragma unroll
        for (int ni = 0; ni < 8; ni++)
            #pragma unroll
            for (int q = 0; q < 4; q++) c[mi][ni][q] = 0.f;

    const int arow = (lane & 7) + ((lane >> 3) & 1) * 8;
    const int akof = (lane >> 4) * 8;
    const int brow = ((lane >> 4) & 1) * 8 + (lane & 7);
    const int bkof = ((lane >> 3) & 1) * 8;

    load_chunk(sb, sb + ATILE_B, A, W, lda, K, bm, bn, 0, tid); cp_commit();
    load_chunk(sb + STAGE_B, sb + STAGE_B + ATILE_B, A, W, lda, K, bm, bn, 1, tid); cp_commit();

    for (int cch = 0; cch < nk; cch++) {
        int st = cch % NSTG;
        if (cch + 1 < nk) cp_wait<1>(); else cp_wait<0>();
        __syncthreads();
        if (cch + 2 < nk) {
            int st2 = (cch + 2) % NSTG;
            load_chunk(sb + st2 * STAGE_B, sb + st2 * STAGE_B + ATILE_B,
                       A, W, lda, K, bm, bn, cch + 2, tid);
            cp_commit();
        }
        uint32_t sA = sb + st * STAGE_B;
        uint32_t sB = sA + ATILE_B;
        #pragma unroll
        for (int kk = 0; kk < 2; kk++) {
            uint32_t a[2][4], b[4][4];
            #pragma unroll
            for (int mi = 0; mi < 2; mi++)
                ldm_x4(a[mi], sA + (wm*32 + mi*16 + arow) * (HSTRIDE*2)
                              + (kk*16 + akof) * 2);
            #pragma unroll
            for (int nt = 0; nt < 4; nt++)
                ldm_x4(b[nt], sB + (wn*64 + nt*16 + brow) * (HSTRIDE*2)
                              + (kk*16 + bkof) * 2);
            #pragma unroll
            for (int mi = 0; mi < 2; mi++)
                #pragma unroll
                for (int ni = 0; ni < 8; ni++)
                    mma16816(c[mi][ni], a[mi], &b[ni >> 1][(ni & 1) * 2]);
        }
        __syncthreads();
    }

    // epilogue
    const int g = lane >> 2;
    const int tc = (lane & 3) * 2;
    #pragma unroll
    for (int mi = 0; mi < 2; mi++) {
        #pragma unroll
        for (int ni = 0; ni < 8; ni++) {
            int row = bm + wm*32 + mi*16 + g;
            int col = bn + wn*64 + ni*8 + tc;
            if (EPI == 3 && col >= Nn) continue;
            float b0 = bias[col], b1 = bias[col + 1];
            #pragma unroll
            for (int half = 0; half < 2; half++) {
                int r = row + half * 8;
                float v0 = c[mi][ni][half*2 + 0] + b0;
                float v1 = c[mi][ni][half*2 + 1] + b1;
                if (EPI == 1) {
                    size_t o = (size_t)r * ldc + col;
                    outf[o]     = v0 + res[o];
                    outf[o + 1] = v1 + res[o + 1];
                } else if (EPI == 3) {
                    size_t o = (size_t)r * ldc + col;
                    outf[o]     = v0;
                    outf[o + 1] = v1;
                } else {
                    if (EPI == 2) {
                        v0 = 0.5f * v0 * (1.0f + erff(v0 * 0.70710678118654752f));
                        v1 = 0.5f * v1 * (1.0f + erff(v1 * 0.70710678118654752f));
                    }
                    *(__half2*)&outh[(size_t)r * ldc + col] =
                        __floats2half2_rn(v0, v1);
                }
            }
        }
    }
}

// ---------------- fp32 -> fp16 convert (all 5 weights in one launch) ----------
#define W1N (3*CC*CC)
#define W2N (CC*CC)
#define W3N (HIDDEN*CC)
#define W4N (CC*HIDDEN)
#define W5R (NOFF*CC)
#define W5N (128*CC)
__global__ void f2h_all(const float* __restrict__ s1, __half* __restrict__ d1,
                        const float* __restrict__ s2, __half* __restrict__ d2,
                        const float* __restrict__ s3, __half* __restrict__ d3,
                        const float* __restrict__ s4, __half* __restrict__ d4,
                        const float* __restrict__ s5, __half* __restrict__ d5)
{
    int i = blockIdx.x * blockDim.x + threadIdx.x;
    int stride = gridDim.x * blockDim.x;
    const int total = W1N + W2N + W3N + W4N + W5N;
    for (; i < total; i += stride) {
        int j = i;
        if (j < W1N) { d1[j] = __float2half(s1[j]); continue; }
        j -= W1N;
        if (j < W2N) { d2[j] = __float2half(s2[j]); continue; }
        j -= W2N;
        if (j < W3N) { d3[j] = __float2half(s3[j]); continue; }
        j -= W3N;
        if (j < W4N) { d4[j] = __float2half(s4[j]); continue; }
        j -= W4N;
        d5[j] = (j < W5R) ? __float2half(s5[j]) : __float2half(0.f);
    }
}

// ---------------- LayerNorm: warp-per-row, shuffle-only reduction ----------------
__global__ void __launch_bounds__(256) ln_kernel(
    const float* __restrict__ x, const float* __restrict__ w,
    const float* __restrict__ b, __half* __restrict__ out)
{
    int row  = blockIdx.x * 8 + (threadIdx.x >> 5);
    int lane = threadIdx.x & 31;
    const float4* xr = (const float4*)(x + (size_t)row * CC);
    const float4* w4 = (const float4*)w;
    const float4* b4 = (const float4*)b;
    __half2* orow = (__half2*)(out + (size_t)row * CC);

    float4 v[6];
    float s = 0.f, s2 = 0.f;
    #pragma unroll
    for (int i = 0; i < 6; i++) {
        v[i] = xr[lane + 32 * i];
        s  += v[i].x + v[i].y + v[i].z + v[i].w;
        s2 += v[i].x*v[i].x + v[i].y*v[i].y + v[i].z*v[i].z + v[i].w*v[i].w;
    }
    #pragma unroll
    for (int o = 16; o; o >>= 1) {
        s  += __shfl_xor_sync(0xffffffffu, s,  o);
        s2 += __shfl_xor_sync(0xffffffffu, s2, o);
    }
    float mean = s * (1.0f / CC);
    float rstd = rsqrtf(s2 * (1.0f / CC) - mean * mean + 1e-5f);

    #pragma unroll
    for (int i = 0; i < 6; i++) {
        int idx = lane + 32 * i;
        float4 ww = w4[idx];
        float4 bb = b4[idx];
        float r0 = (v[i].x - mean) * rstd * ww.x + bb.x;
        float r1 = (v[i].y - mean) * rstd * ww.y + bb.y;
        float r2 = (v[i].z - mean) * rstd * ww.z + bb.z;
        float r3 = (v[i].w - mean) * rstd * ww.w + bb.w;
        orow[idx * 2 + 0] = __floats2half2_rn(r0, r1);
        orow[idx * 2 + 1] = __floats2half2_rn(r2, r3);
    }
}

// ---------------- Fused deformable attention: one warp per (b, n, h) -----------
// __half2 gathers + __half2 bilinear accumulation (halves fma-pipe work).
__global__ void attn_kernel(const __half* __restrict__ qkv, const float* __restrict__ off,
                            const float* __restrict__ ref, __half* __restrict__ out)
{
    int gw = (blockIdx.x * blockDim.x + threadIdx.x) >> 5;
    int lane = threadIdx.x & 31;
    if (gw >= BB * NN * NHEADS) return;
    int h  = gw % NHEADS;
    int bn = gw / NHEADS;
    int b  = bn / NN;

    float refx = ref[(size_t)bn * 2 + 0];
    float refy = ref[(size_t)bn * 2 + 1];

    const __half2* qkv2 = (const __half2*)qkv;
    size_t qidx = ((size_t)bn * (3 * CC) + h * HDIM) / 2 + lane;
    float2 q = __half22float2(qkv2[qidx]);

    const float* obp = off + (size_t)bn * NOFF + h * NPTS * 2;
    size_t imgbase2 = ((size_t)b * NN * (3 * CC)) / 2;
    int choff2 = (h * HDIM) / 2 + lane;

    float dots[NPTS];
    float2 vv[NPTS];
    #pragma unroll
    for (int p = 0; p < NPTS; p++) {
        float xp = refx * 64.f + obp[p * 2 + 0] - 0.5f;
        float yp = refy * 64.f + obp[p * 2 + 1] - 0.5f;
        float x0f = floorf(xp), y0f = floorf(yp);
        float wx = xp - x0f, wy = yp - y0f;
        int ix0 = (int)x0f, iy0 = (int)y0f;

        float cw[4] = {(1.f - wx) * (1.f - wy), wx * (1.f - wy),
                       (1.f - wx) * wy,          wx * wy};
        int cx[4] = {ix0, ix0 + 1, ix0, ix0 + 1};
        int cy[4] = {iy0, iy0, iy0 + 1, iy0 + 1};

        __half2 ks = __float2half2_rn(0.f), vs = __float2half2_rn(0.f);
        #pragma unroll
        for (int c = 0; c < 4; c++) {
            if (cx[c] >= 0 && cx[c] < 64 && cy[c] >= 0 && cy[c] < 64) {
                size_t base2 = imgbase2 + (size_t)(cy[c] * 64 + cx[c]) * ((3 * CC) / 2) + choff2;
                __half2 wgt2 = __float2half2_rn(cw[c]);
                ks = __hfma2(qkv2[base2 + CC / 2], wgt2, ks);
                vs = __hfma2(qkv2[base2 + CC],     wgt2, vs);
            }
        }
        float2 kf = __half22float2(ks);
        float d = q.x * kf.x + q.y * kf.y;
        #pragma unroll
        for (int o = 16; o; o >>= 1) d += __shfl_xor_sync(0xffffffffu, d, o);
        dots[p] = d * 0.125f;
        vv[p] = __half22float2(vs);
    }

    float mx = fmaxf(fmaxf(dots[0], dots[1]), fmaxf(dots[2], dots[3]));
    float e[NPTS], den = 0.f;
    #pragma unroll
    for (int p = 0; p < NPTS; p++) { e[p] = expf(dots[p] - mx); den += e[p]; }
    float inv = 1.f / den;
    float o0 = 0.f, o1 = 0.f;
    #pragma unroll
    for (int p = 0; p < NPTS; p++) {
        float a = e[p] * inv;
        o0 += a * vv[p].x; o1 += a * vv[p].y;
    }

    __half2* out2 = (__half2*)out;
    out2[((size_t)bn * CC + h * HDIM) / 2 + lane] = __floats2half2_rn(o0, o1);
}

// ---------------- launch ----------------
extern "C" void kernel_launch(void* const* d_in, const int* in_sizes, int n_in,
                              void* d_out, int out_size)
{
    const float* x    = (const float*)d_in[0];
    const float* ref  = (const float*)d_in[1];
    const float* n1w  = (const float*)d_in[2];
    const float* n1b  = (const float*)d_in[3];
    const float* qkvw = (const float*)d_in[4];
    const float* qkvb = (const float*)d_in[5];
    const float* offw = (const float*)d_in[6];
    const float* offb = (const float*)d_in[7];
    const float* pw   = (const float*)d_in[8];
    const float* pb   = (const float*)d_in[9];
    const float* n2w  = (const float*)d_in[10];
    const float* n2b  = (const float*)d_in[11];
    const float* f1w  = (const float*)d_in[12];
    const float* f1b  = (const float*)d_in[13];
    const float* f2w  = (const float*)d_in[14];
    const float* f2b  = (const float*)d_in[15];
    float* out = (float*)d_out;

    __half *h_, *qkv_, *att_, *h2_, *mid_, *qkvw_h, *pw_h, *f1w_h, *f2w_h, *offw_h;
    float *off_, *x2_;
    cudaGetSymbolAddress((void**)&h_,     g_h);
    cudaGetSymbolAddress((void**)&qkv_,   g_qkv);
    cudaGetSymbolAddress((void**)&off_,   g_off);
    cudaGetSymbolAddress((void**)&att_,   g_att);
    cudaGetSymbolAddress((void**)&x2_,    g_x2);
    cudaGetSymbolAddress((void**)&h2_,    g_h2);
    cudaGetSymbolAddress((void**)&mid_,   g_mid);
    cudaGetSymbolAddress((void**)&qkvw_h, g_qkvw_h);
    cudaGetSymbolAddress((void**)&pw_h,   g_pw_h);
    cudaGetSymbolAddress((void**)&f1w_h,  g_f1w_h);
    cudaGetSymbolAddress((void**)&f2w_h,  g_f2w_h);
    cudaGetSymbolAddress((void**)&offw_h, g_offw_h);

    cudaFuncSetAttribute(hgemm<0>, cudaFuncAttributeMaxDynamicSharedMemorySize, HG_SMEM);
    cudaFuncSetAttribute(hgemm<1>, cudaFuncAttributeMaxDynamicSharedMemorySize, HG_SMEM);
    cudaFuncSetAttribute(hgemm<2>, cudaFuncAttributeMaxDynamicSharedMemorySize, HG_SMEM);
    cudaFuncSetAttribute(hgemm<3>, cudaFuncAttributeMaxDynamicSharedMemorySize, HG_SMEM);

    // 0. weight conversions to fp16 (single launch)
    f2h_all<<<2048, 256>>>(qkvw, qkvw_h, pw, pw_h, f1w, f1w_h, f2w, f2w_h, offw, offw_h);

    // 1. h = LN1(x)
    ln_kernel<<<MROWS / 8, 256>>>(x, n1w, n1b, h_);
    // 2. qkv = h @ qkv_w.T + qkv_b  [16384, 2304]
    hgemm<0><<<dim3(18, 128), 256, HG_SMEM>>>(h_, qkvw_h, qkvb, nullptr,
                                              qkv_, nullptr, CC, CC, 3 * CC, 3 * CC);
    // 3. offsets = q @ off_w.T + off_b  [16384, 96]
    hgemm<3><<<dim3(1, 128), 256, HG_SMEM>>>(qkv_, offw_h, offb, nullptr,
                                             nullptr, off_, 3 * CC, CC, NOFF, NOFF);
    // 4. fused grid-sample attention
    attn_kernel<<<(BB * NN * NHEADS * 32) / 256, 256>>>(qkv_, off_, ref, att_);
    // 5. x2 = x + att @ proj_w.T + proj_b
    hgemm<1><<<dim3(6, 128), 256, HG_SMEM>>>(att_, pw_h, pb, x,
                                             nullptr, x2_, CC, CC, CC, CC);
    // 6. h2 = LN2(x2)
    ln_kernel<<<MROWS / 8, 256>>>(x2_, n2w, n2b, h2_);
    // 7. mid = gelu(h2 @ fc1_w.T + fc1_b)  [16384, 3072]
    hgemm<2><<<dim3(24, 128), 256, HG_SMEM>>>(h2_, f1w_h, f1b, nullptr,
                                              mid_, nullptr, CC, CC, HIDDEN, HIDDEN);
    // 8. out = x2 + mid @ fc2_w.T + fc2_b
    hgemm<1><<<dim3(6, 128), 256, HG_SMEM>>>(mid_, f2w_h, f2b, x2_,
                                             nullptr, out, HIDDEN, HIDDEN, CC, CC);
}